// round 3
// baseline (speedup 1.0000x reference)
#include <cuda_runtime.h>

#define NN 100000
#define MAXE 3200000

// ---- static scratch (no allocations allowed) ----
__device__ int   g_is64;
__device__ int   g_deg[NN];
__device__ int   g_rowptr[NN + 1];
__device__ int   g_cursor[NN];
__device__ int   g_col[MAXE];
__device__ float g_dinv[NN];
__device__ float g_xw1[(size_t)NN * 256];
__device__ float g_z1 [(size_t)NN * 256];
__device__ float g_xw2[(size_t)NN * 128];
__device__ float g_z2 [(size_t)NN * 128];

// Buffer selector: 0 = kernel argument, 1..4 = device-global scratch.
__device__ __forceinline__ const float* sel_src(int id, const float* arg) {
    switch (id) {
        case 1: return g_xw1;
        case 2: return g_z1;
        case 3: return g_xw2;
        case 4: return g_z2;
        default: return arg;
    }
}
__device__ __forceinline__ float* sel_dst(int id, float* arg) {
    switch (id) {
        case 1: return g_xw1;
        case 2: return g_z1;
        case 3: return g_xw2;
        case 4: return g_z2;
        default: return arg;
    }
}

// ---------------- edge-index dtype detection ----------------
// If the buffer is int64, the high 32-bit word of every entry is 0
// (all indices in [0, 100000)). If it is int32, those words are random
// indices — effectively never all zero over 2048 samples.
__global__ void k_detect(const int* __restrict__ ei32, int E) {
    __shared__ int bad;
    if (threadIdx.x == 0) bad = 0;
    __syncthreads();
    int n = min(E, 2048);
    for (int i = threadIdx.x; i < n; i += blockDim.x)
        if (ei32[2 * i + 1] != 0) bad = 1;
    __syncthreads();
    if (threadIdx.x == 0) g_is64 = bad ? 0 : 1;
}

__device__ __forceinline__ int load_idx(const void* ei, long long pos) {
    if (g_is64) return (int)((const long long*)ei)[pos];
    return ((const int*)ei)[pos];
}

// ---------------- graph prep ----------------
__global__ void k_zero_deg() {
    int i = blockIdx.x * blockDim.x + threadIdx.x;
    if (i < NN) g_deg[i] = 0;
}

__global__ void k_count(const void* __restrict__ ei, int E) {
    int e = blockIdx.x * blockDim.x + threadIdx.x;
    if (e < E) {
        int r = load_idx(ei, e);
        if ((unsigned)r < NN) atomicAdd(&g_deg[r], 1);
    }
}

// single-block exclusive scan of g_deg -> g_rowptr, plus dinv = rsqrt(deg+1)
__global__ void k_scan() {
    const int CH = (NN + 1023) / 1024;
    __shared__ int ps[1024];
    int t = threadIdx.x;
    int beg = t * CH;
    int end = min(beg + CH, NN);
    int s = 0;
    for (int i = beg; i < end; i++) s += g_deg[i];
    ps[t] = s;
    __syncthreads();
    for (int off = 1; off < 1024; off <<= 1) {
        int v = (t >= off) ? ps[t - off] : 0;
        __syncthreads();
        ps[t] += v;
        __syncthreads();
    }
    int run = (t > 0) ? ps[t - 1] : 0;
    for (int i = beg; i < end; i++) {
        int d = g_deg[i];
        g_rowptr[i] = run;
        g_cursor[i] = run;
        g_dinv[i]   = rsqrtf((float)(d + 1));  // +1 self loop
        run += d;
    }
    if (t == 0) g_rowptr[NN] = ps[1023];
}

__global__ void k_fill(const void* __restrict__ ei, int E) {
    int e = blockIdx.x * blockDim.x + threadIdx.x;
    if (e < E) {
        int r = load_idx(ei, e);
        if ((unsigned)r < NN) {
            int c = load_idx(ei, (long long)E + e);
            if ((unsigned)c >= NN) c = 0;  // safety clamp (never hit if dtype right)
            int p = atomicAdd(&g_cursor[r], 1);
            g_col[p] = c;
        }
    }
}

// ---------------- SGEMM: C[M,N] = A[M,K] @ B[K,N] (+bias) ----------------
// 64x64 tile, BK=16, 256 threads, 4x4 microtile per thread.
template <int ASRC, int CDST, bool BIAS>
__global__ void sgemm(const float* __restrict__ Aarg, const float* __restrict__ B,
                      const float* __restrict__ bias, float* __restrict__ Carg,
                      int M, int N, int K) {
    const float* A = sel_src(ASRC, Aarg);
    float*       C = sel_dst(CDST, Carg);

    __shared__ float As[16][64];
    __shared__ float Bs[16][64];
    int tid = threadIdx.x;
    int bm = blockIdx.x * 64;
    int bn = blockIdx.y * 64;
    int tx = tid & 15, ty = tid >> 4;

    int arow = tid >> 2;          // 0..63
    int acol = (tid & 3) * 4;     // 0,4,8,12
    int brow = tid >> 4;          // 0..15
    int bcol = (tid & 15) * 4;    // 0..60

    float acc[4][4];
#pragma unroll
    for (int i = 0; i < 4; i++)
#pragma unroll
        for (int j = 0; j < 4; j++) acc[i][j] = 0.f;

    bool avalid = (bm + arow) < M;
    const float* Aptr = A + (size_t)(bm + arow) * K + acol;
    const float* Bptr = B + (size_t)brow * N + bn + bcol;

    for (int k0 = 0; k0 < K; k0 += 16) {
        float4 av = avalid ? *(const float4*)(Aptr + k0) : make_float4(0.f, 0.f, 0.f, 0.f);
        float4 bv = *(const float4*)(Bptr + (size_t)k0 * N);
        As[acol + 0][arow] = av.x;
        As[acol + 1][arow] = av.y;
        As[acol + 2][arow] = av.z;
        As[acol + 3][arow] = av.w;
        *(float4*)&Bs[brow][bcol] = bv;
        __syncthreads();
#pragma unroll
        for (int k = 0; k < 16; k++) {
            float a[4], b[4];
#pragma unroll
            for (int i = 0; i < 4; i++) a[i] = As[k][ty * 4 + i];
#pragma unroll
            for (int j = 0; j < 4; j++) b[j] = Bs[k][tx * 4 + j];
#pragma unroll
            for (int i = 0; i < 4; i++)
#pragma unroll
                for (int j = 0; j < 4; j++) acc[i][j] += a[i] * b[j];
        }
        __syncthreads();
    }

#pragma unroll
    for (int i = 0; i < 4; i++) {
        int r = bm + ty * 4 + i;
        if (r < M) {
#pragma unroll
            for (int j = 0; j < 4; j++) {
                int c = bn + tx * 4 + j;
                float v = acc[i][j];
                if (BIAS) v += bias[c];
                C[(size_t)r * N + c] = v;
            }
        }
    }
}

// ---------------- GCN propagate (gather form) ----------------
// out[i] = dinv[i] * ( dinv[i]*xw[i] + sum_{e in row i} dinv[col_e]*xw[col_e] ) + bias
template <int F, bool RELU, int SRC, int DST>
__global__ void k_prop(const float* __restrict__ bias) {
    const float* xw  = sel_src(SRC, nullptr);
    float*       out = sel_dst(DST, nullptr);
    int i = blockIdx.x;
    int f = threadIdx.x;
    float di = g_dinv[i];
    float acc = di * xw[(size_t)i * F + f];  // self loop (one di factored out)
    int s = g_rowptr[i];
    int e = g_rowptr[i + 1];
    for (int k = s; k < e; k++) {
        int c = g_col[k];  // broadcast across block
        acc += g_dinv[c] * xw[(size_t)c * F + f];
    }
    float v = di * acc + bias[f];
    if (RELU) v = fmaxf(v, 0.f);
    out[(size_t)i * F + f] = v;
}

// ---------------- launch ----------------
extern "C" void kernel_launch(void* const* d_in, const int* in_sizes, int n_in,
                              void* d_out, int out_size) {
    const float* x   = (const float*)d_in[0];
    const void*  ei  = d_in[1];
    const float* W1  = (const float*)d_in[2];
    const float* b1  = (const float*)d_in[3];
    const float* W2  = (const float*)d_in[4];
    const float* b2  = (const float*)d_in[5];
    const float* Wmu = (const float*)d_in[6];
    const float* bmu = (const float*)d_in[7];
    const float* Wlv = (const float*)d_in[8];
    const float* blv = (const float*)d_in[9];
    float* out = (float*)d_out;

    int E = in_sizes[1] / 2;

    // graph prep (shared by both GCN layers)
    k_detect<<<1, 256>>>((const int*)ei, E);
    k_zero_deg<<<(NN + 255) / 256, 256>>>();
    k_count<<<(E + 255) / 256, 256>>>(ei, E);
    k_scan<<<1, 1024>>>();
    k_fill<<<(E + 255) / 256, 256>>>(ei, E);

    // layer 1: xw1 = x @ W1 ; z1 = relu(prop(xw1) + b1)
    sgemm<0, 1, false><<<dim3((NN + 63) / 64, 256 / 64), 256>>>(x, W1, nullptr, nullptr, NN, 256, 256);
    k_prop<256, true, 1, 2><<<NN, 256>>>(b1);

    // layer 2: xw2 = z1 @ W2 ; z2 = prop(xw2) + b2
    sgemm<2, 3, false><<<dim3((NN + 63) / 64, 128 / 64), 256>>>(nullptr, W2, nullptr, nullptr, NN, 128, 256);
    k_prop<128, false, 3, 4><<<NN, 128>>>(b2);

    // heads: mu, logvar
    sgemm<4, 0, true><<<dim3((NN + 63) / 64, 128 / 64), 256>>>(nullptr, Wmu, bmu, out, NN, 128, 128);
    sgemm<4, 0, true><<<dim3((NN + 63) / 64, 128 / 64), 256>>>(nullptr, Wlv, blv, out + (size_t)NN * 128, NN, 128, 128);
}

// round 4
// speedup vs baseline: 1.7083x; 1.7083x over previous
#include <cuda_runtime.h>

#define NN 100000
#define MAXE 3200000
#define SCAN_B 100
#define SCAN_CH 1000   // SCAN_B * SCAN_CH == NN exactly

// ---- static scratch ----
__device__ int   g_is64;
__device__ int   g_deg[NN];
__device__ int   g_rowptr[NN + 1];
__device__ int   g_cursor[NN];
__device__ int   g_col[MAXE];
__device__ float g_dinv[NN];
__device__ int   g_bsum[SCAN_B];
__device__ int   g_boff[SCAN_B + 1];
__device__ float g_xw1[(size_t)NN * 256];
__device__ float g_z1 [(size_t)NN * 256];
__device__ float g_xw2[(size_t)NN * 128];
__device__ float g_z2 [(size_t)NN * 128];

__device__ __forceinline__ const float* sel_src(int id, const float* arg) {
    switch (id) {
        case 1: return g_xw1;
        case 2: return g_z1;
        case 3: return g_xw2;
        case 4: return g_z2;
        default: return arg;
    }
}
__device__ __forceinline__ float* sel_dst(int id, float* arg) {
    switch (id) {
        case 1: return g_xw1;
        case 2: return g_z1;
        case 3: return g_xw2;
        case 4: return g_z2;
        default: return arg;
    }
}

// ---------------- edge-index dtype detection ----------------
__global__ void k_detect(const int* __restrict__ ei32, int E) {
    __shared__ int bad;
    if (threadIdx.x == 0) bad = 0;
    __syncthreads();
    int n = min(E, 2048);
    for (int i = threadIdx.x; i < n; i += blockDim.x)
        if (ei32[2 * i + 1] != 0) bad = 1;
    __syncthreads();
    if (threadIdx.x == 0) g_is64 = bad ? 0 : 1;
}

__device__ __forceinline__ int load_idx(const void* ei, long long pos) {
    if (g_is64) return (int)((const long long*)ei)[pos];
    return ((const int*)ei)[pos];
}

// ---------------- graph prep ----------------
__global__ void k_zero_deg() {
    int i = blockIdx.x * blockDim.x + threadIdx.x;
    if (i < NN) g_deg[i] = 0;
}

__global__ void k_count(const void* __restrict__ ei, int E) {
    int e = blockIdx.x * blockDim.x + threadIdx.x;
    if (e < E) {
        int r = load_idx(ei, e);
        if ((unsigned)r < NN) atomicAdd(&g_deg[r], 1);
    }
}

// phase 1: per-block partial sums of g_deg
__global__ void k_reduce() {
    __shared__ int sh[256];
    int b = blockIdx.x, t = threadIdx.x;
    int s = 0;
    int base = b * SCAN_CH;
    for (int i = t; i < SCAN_CH; i += 256) s += g_deg[base + i];
    sh[t] = s;
    __syncthreads();
    for (int off = 128; off > 0; off >>= 1) {
        if (t < off) sh[t] += sh[t + off];
        __syncthreads();
    }
    if (t == 0) g_bsum[b] = sh[0];
}

// phase 2: exclusive scan of the SCAN_B block sums
__global__ void k_scan_bsums() {
    __shared__ int sh[128];
    int t = threadIdx.x;
    int v = (t < SCAN_B) ? g_bsum[t] : 0;
    sh[t] = v;
    __syncthreads();
    for (int off = 1; off < 128; off <<= 1) {
        int u = (t >= off) ? sh[t - off] : 0;
        __syncthreads();
        sh[t] += u;
        __syncthreads();
    }
    if (t < SCAN_B) g_boff[t] = sh[t] - v;   // exclusive
    if (t == SCAN_B - 1) {
        g_boff[SCAN_B] = sh[t];
        g_rowptr[NN] = sh[t];
    }
}

// phase 3: per-block local exclusive scan + rowptr/cursor/dinv
__global__ void k_scan_final() {
    __shared__ int ps[256];
    int b = blockIdx.x, t = threadIdx.x;
    int base = b * SCAN_CH;
    int d[4];
    int my = 0;
    if (t < 250) {
#pragma unroll
        for (int j = 0; j < 4; j++) {
            d[j] = g_deg[base + t * 4 + j];
            my += d[j];
        }
    }
    ps[t] = my;
    __syncthreads();
    for (int off = 1; off < 256; off <<= 1) {
        int u = (t >= off) ? ps[t - off] : 0;
        __syncthreads();
        ps[t] += u;
        __syncthreads();
    }
    if (t < 250) {
        int run = g_boff[b] + ps[t] - my;   // exclusive prefix
#pragma unroll
        for (int j = 0; j < 4; j++) {
            int i = base + t * 4 + j;
            g_rowptr[i] = run;
            g_cursor[i] = run;
            g_dinv[i]   = rsqrtf((float)(d[j] + 1));
            run += d[j];
        }
    }
}

__global__ void k_fill(const void* __restrict__ ei, int E) {
    int e = blockIdx.x * blockDim.x + threadIdx.x;
    if (e < E) {
        int r = load_idx(ei, e);
        if ((unsigned)r < NN) {
            int c = load_idx(ei, (long long)E + e);
            if ((unsigned)c >= NN) c = 0;
            int p = atomicAdd(&g_cursor[r], 1);
            g_col[p] = c;
        }
    }
}

// ---------------- SGEMM 128x128, BK=8, 256 thr, 8x8 micro, double-buffered ----
// SCALE: C[r][c] = dinv[r] * sum   (pre-scales xw for the propagate step)
template <int ASRC, int CDST, bool BIAS, bool SCALE>
__global__ void __launch_bounds__(256, 2)
sgemm128(const float* __restrict__ Aarg, const float* __restrict__ B,
         const float* __restrict__ bias, float* __restrict__ Carg,
         int M, int N, int K) {
    const float* A = sel_src(ASRC, Aarg);
    float*       C = sel_dst(CDST, Carg);

    __shared__ float As[2][8][128];
    __shared__ float Bs[2][8][128];

    int tid = threadIdx.x;
    int bm = blockIdx.x * 128, bn = blockIdx.y * 128;
    int arow = tid >> 1, akc = (tid & 1) * 4;        // A: 128 rows x 8 k
    int brow = tid >> 5, bcol = (tid & 31) * 4;      // B: 8 k x 128 cols
    int tx = tid & 15, ty = tid >> 4;

    bool aval = (bm + arow) < M;
    const float* Ap = A + (size_t)(bm + arow) * K + akc;
    const float* Bp = B + (size_t)brow * N + bn + bcol;

    float4 av = aval ? *(const float4*)Ap : make_float4(0.f, 0.f, 0.f, 0.f);
    float4 bv = *(const float4*)Bp;

    As[0][akc + 0][arow] = av.x;
    As[0][akc + 1][arow] = av.y;
    As[0][akc + 2][arow] = av.z;
    As[0][akc + 3][arow] = av.w;
    *(float4*)&Bs[0][brow][bcol] = bv;
    __syncthreads();

    float acc[8][8];
#pragma unroll
    for (int i = 0; i < 8; i++)
#pragma unroll
        for (int j = 0; j < 8; j++) acc[i][j] = 0.f;

    int stage = 0;
    for (int k0 = 0; k0 < K; k0 += 8) {
        bool more = (k0 + 8) < K;
        if (more) {
            av = aval ? *(const float4*)(Ap + k0 + 8) : make_float4(0.f, 0.f, 0.f, 0.f);
            bv = *(const float4*)(Bp + (size_t)(k0 + 8) * N);
        }
#pragma unroll
        for (int k = 0; k < 8; k++) {
            float a[8], b[8];
            *(float4*)&a[0] = *(const float4*)&As[stage][k][ty * 4];
            *(float4*)&a[4] = *(const float4*)&As[stage][k][64 + ty * 4];
            *(float4*)&b[0] = *(const float4*)&Bs[stage][k][tx * 4];
            *(float4*)&b[4] = *(const float4*)&Bs[stage][k][64 + tx * 4];
#pragma unroll
            for (int i = 0; i < 8; i++)
#pragma unroll
                for (int j = 0; j < 8; j++) acc[i][j] += a[i] * b[j];
        }
        if (more) {
            stage ^= 1;
            As[stage][akc + 0][arow] = av.x;
            As[stage][akc + 1][arow] = av.y;
            As[stage][akc + 2][arow] = av.z;
            As[stage][akc + 3][arow] = av.w;
            *(float4*)&Bs[stage][brow][bcol] = bv;
            __syncthreads();
        }
    }

    // epilogue: rows {bm+ty*4+i, bm+64+ty*4+i}, cols {bn+tx*4+j, bn+64+tx*4+j}
#pragma unroll
    for (int ih = 0; ih < 2; ih++) {
#pragma unroll
        for (int i = 0; i < 4; i++) {
            int r = bm + ih * 64 + ty * 4 + i;
            if (r >= M) continue;
            float sc = SCALE ? g_dinv[r] : 1.f;
#pragma unroll
            for (int jh = 0; jh < 2; jh++) {
                int c0 = bn + jh * 64 + tx * 4;
                float4 v;
                v.x = acc[ih * 4 + i][jh * 4 + 0];
                v.y = acc[ih * 4 + i][jh * 4 + 1];
                v.z = acc[ih * 4 + i][jh * 4 + 2];
                v.w = acc[ih * 4 + i][jh * 4 + 3];
                if (SCALE) { v.x *= sc; v.y *= sc; v.z *= sc; v.w *= sc; }
                if (BIAS) {
                    v.x += bias[c0 + 0];
                    v.y += bias[c0 + 1];
                    v.z += bias[c0 + 2];
                    v.w += bias[c0 + 3];
                }
                *(float4*)&C[(size_t)r * N + c0] = v;
            }
        }
    }
}

// ---------------- GCN propagate ----------------
// xw is PRE-SCALED by dinv.  out[i] = dinv[i]*(xw[i] + sum_e xw[col_e]) + bias
template <int F, bool RELU, int SRC, int DST, int NPB>
__global__ void k_prop(const float* __restrict__ bias) {
    int node = blockIdx.x * NPB + threadIdx.y;
    if (node >= NN) return;
    const float4* xw  = (const float4*)sel_src(SRC, nullptr);
    float4*       out = (float4*)sel_dst(DST, nullptr);
    int f = threadIdx.x;  // F/4 lanes
    const int F4 = F / 4;

    float4 acc = xw[(size_t)node * F4 + f];  // self loop (prescaled)
    int s = g_rowptr[node];
    int e = g_rowptr[node + 1];
    for (int k = s; k < e; k++) {
        int c = g_col[k];
        float4 v = xw[(size_t)c * F4 + f];
        acc.x += v.x; acc.y += v.y; acc.z += v.z; acc.w += v.w;
    }
    float di = g_dinv[node];
    float4 b4 = ((const float4*)bias)[f];
    float4 r;
    r.x = di * acc.x + b4.x;
    r.y = di * acc.y + b4.y;
    r.z = di * acc.z + b4.z;
    r.w = di * acc.w + b4.w;
    if (RELU) {
        r.x = fmaxf(r.x, 0.f); r.y = fmaxf(r.y, 0.f);
        r.z = fmaxf(r.z, 0.f); r.w = fmaxf(r.w, 0.f);
    }
    out[(size_t)node * F4 + f] = r;
}

// ---------------- launch ----------------
extern "C" void kernel_launch(void* const* d_in, const int* in_sizes, int n_in,
                              void* d_out, int out_size) {
    const float* x   = (const float*)d_in[0];
    const void*  ei  = d_in[1];
    const float* W1  = (const float*)d_in[2];
    const float* b1  = (const float*)d_in[3];
    const float* W2  = (const float*)d_in[4];
    const float* b2  = (const float*)d_in[5];
    const float* Wmu = (const float*)d_in[6];
    const float* bmu = (const float*)d_in[7];
    const float* Wlv = (const float*)d_in[8];
    const float* blv = (const float*)d_in[9];
    float* out = (float*)d_out;

    int E = in_sizes[1] / 2;

    // graph prep
    k_detect<<<1, 256>>>((const int*)ei, E);
    k_zero_deg<<<(NN + 255) / 256, 256>>>();
    k_count<<<(E + 255) / 256, 256>>>(ei, E);
    k_reduce<<<SCAN_B, 256>>>();
    k_scan_bsums<<<1, 128>>>();
    k_scan_final<<<SCAN_B, 256>>>();
    k_fill<<<(E + 255) / 256, 256>>>(ei, E);

    dim3 g1((NN + 127) / 128, 256 / 128);
    dim3 g2((NN + 127) / 128, 128 / 128);

    // layer 1: xw1 = dinv * (x @ W1) ; z1 = relu(prop + b1)
    sgemm128<0, 1, false, true><<<g1, 256>>>(x, W1, nullptr, nullptr, NN, 256, 256);
    k_prop<256, true, 1, 2, 2><<<(NN + 1) / 2, dim3(64, 2)>>>(b1);

    // layer 2: xw2 = dinv * (z1 @ W2) ; z2 = prop + b2
    sgemm128<2, 3, false, true><<<g2, 256>>>(nullptr, W2, nullptr, nullptr, NN, 128, 256);
    k_prop<128, false, 3, 4, 4><<<(NN + 3) / 4, dim3(32, 4)>>>(b2);

    // heads
    sgemm128<4, 0, true, false><<<g2, 256>>>(nullptr, Wmu, bmu, out, NN, 128, 128);
    sgemm128<4, 0, true, false><<<g2, 256>>>(nullptr, Wlv, blv, out + (size_t)NN * 128, NN, 128, 128);
}

// round 6
// speedup vs baseline: 2.5003x; 1.4636x over previous
#include <cuda_runtime.h>
#include <cuda_fp16.h>
#include <cuda_bf16.h>
#include <cstdint>

#define NN 100000
#define MAXE 3200000
#define SCAN_B 100
#define SCAN_CH 1000

// ---- static scratch ----
__device__ int   g_is64;
__device__ int   g_deg[NN];
__device__ int   g_rowptr[NN + 1];
__device__ int   g_cursor[NN];
__device__ int   g_col[MAXE];
__device__ float g_dinv[NN];
__device__ int   g_bsum[SCAN_B];
__device__ int   g_boff[SCAN_B + 1];

// activations
__device__ __half g_xw1h[(size_t)NN * 256];  // dinv-prescaled, prop input L1
__device__ __half g_xw2h[(size_t)NN * 128];  // prop input L2
__device__ float  g_z1 [(size_t)NN * 256];
__device__ float  g_z2 [(size_t)NN * 128];

// weight splits, [N,K] layout (B operand), bf16 hi/lo
__device__ unsigned short g_w1h[256 * 256], g_w1l[256 * 256];
__device__ unsigned short g_w2h[128 * 256], g_w2l[128 * 256];
__device__ unsigned short g_wmuh[128 * 128], g_wmul[128 * 128];
__device__ unsigned short g_wlvh[128 * 128], g_wlvl[128 * 128];

__device__ __forceinline__ const unsigned short* sel_wh(int id) {
    switch (id) { case 1: return g_w1h; case 2: return g_w2h;
                  case 3: return g_wmuh; default: return g_wlvh; }
}
__device__ __forceinline__ const unsigned short* sel_wl(int id) {
    switch (id) { case 1: return g_w1l; case 2: return g_w2l;
                  case 3: return g_wmul; default: return g_wlvl; }
}
__device__ __forceinline__ const float* sel_af(int id, const float* arg) {
    switch (id) { case 2: return g_z1; case 4: return g_z2; default: return arg; }
}
__device__ __forceinline__ __half* sel_d16(int id) {
    return (id == 1) ? g_xw1h : g_xw2h;
}

__device__ __forceinline__ uint32_t smem_u32(const void* p) {
    uint32_t a;
    asm("{ .reg .u64 t; cvta.to.shared.u64 t, %1; cvt.u32.u64 %0, t; }"
        : "=r"(a) : "l"(p));
    return a;
}

#define LDSM4(r, addr)                                                         \
    asm volatile("ldmatrix.sync.aligned.m8n8.x4.shared.b16 {%0,%1,%2,%3}, [%4];" \
                 : "=r"((r)[0]), "=r"((r)[1]), "=r"((r)[2]), "=r"((r)[3])      \
                 : "r"(addr))

__device__ __forceinline__ void mma16816(float* c, const uint32_t* a,
                                         uint32_t b0, uint32_t b1) {
    asm volatile(
        "mma.sync.aligned.m16n8k16.row.col.f32.bf16.bf16.f32 "
        "{%0,%1,%2,%3}, {%4,%5,%6,%7}, {%8,%9}, {%0,%1,%2,%3};"
        : "+f"(c[0]), "+f"(c[1]), "+f"(c[2]), "+f"(c[3])
        : "r"(a[0]), "r"(a[1]), "r"(a[2]), "r"(a[3]), "r"(b0), "r"(b1));
}

// ================= edge-index prep =================
__global__ void k_detect(const int* __restrict__ ei32, int E) {
    __shared__ int bad;
    if (threadIdx.x == 0) bad = 0;
    __syncthreads();
    int n = min(E, 2048);
    for (int i = threadIdx.x; i < n; i += blockDim.x)
        if (ei32[2 * i + 1] != 0) bad = 1;
    __syncthreads();
    if (threadIdx.x == 0) g_is64 = bad ? 0 : 1;
}
__device__ __forceinline__ int load_idx(const void* ei, long long pos) {
    if (g_is64) return (int)((const long long*)ei)[pos];
    return ((const int*)ei)[pos];
}
__global__ void k_zero_deg() {
    int i = blockIdx.x * blockDim.x + threadIdx.x;
    if (i < NN) g_deg[i] = 0;
}
__global__ void k_count(const void* __restrict__ ei, int E) {
    int e = blockIdx.x * blockDim.x + threadIdx.x;
    if (e < E) {
        int r = load_idx(ei, e);
        if ((unsigned)r < NN) atomicAdd(&g_deg[r], 1);
    }
}
__global__ void k_reduce() {
    __shared__ int sh[256];
    int b = blockIdx.x, t = threadIdx.x, s = 0, base = b * SCAN_CH;
    for (int i = t; i < SCAN_CH; i += 256) s += g_deg[base + i];
    sh[t] = s;
    __syncthreads();
    for (int off = 128; off > 0; off >>= 1) {
        if (t < off) sh[t] += sh[t + off];
        __syncthreads();
    }
    if (t == 0) g_bsum[b] = sh[0];
}
__global__ void k_scan_bsums() {
    __shared__ int sh[128];
    int t = threadIdx.x;
    int v = (t < SCAN_B) ? g_bsum[t] : 0;
    sh[t] = v;
    __syncthreads();
    for (int off = 1; off < 128; off <<= 1) {
        int u = (t >= off) ? sh[t - off] : 0;
        __syncthreads();
        sh[t] += u;
        __syncthreads();
    }
    if (t < SCAN_B) g_boff[t] = sh[t] - v;
    if (t == SCAN_B - 1) { g_boff[SCAN_B] = sh[t]; g_rowptr[NN] = sh[t]; }
}
__global__ void k_scan_final() {
    __shared__ int ps[256];
    int b = blockIdx.x, t = threadIdx.x, base = b * SCAN_CH;
    int d[4], my = 0;
    if (t < 250) {
#pragma unroll
        for (int j = 0; j < 4; j++) { d[j] = g_deg[base + t * 4 + j]; my += d[j]; }
    }
    ps[t] = my;
    __syncthreads();
    for (int off = 1; off < 256; off <<= 1) {
        int u = (t >= off) ? ps[t - off] : 0;
        __syncthreads();
        ps[t] += u;
        __syncthreads();
    }
    if (t < 250) {
        int run = g_boff[b] + ps[t] - my;
#pragma unroll
        for (int j = 0; j < 4; j++) {
            int i = base + t * 4 + j;
            g_rowptr[i] = run;
            g_cursor[i] = run;
            g_dinv[i]   = rsqrtf((float)(d[j] + 1));
            run += d[j];
        }
    }
}
__global__ void k_fill(const void* __restrict__ ei, int E) {
    int e = blockIdx.x * blockDim.x + threadIdx.x;
    if (e < E) {
        int r = load_idx(ei, e);
        if ((unsigned)r < NN) {
            int c = load_idx(ei, (long long)E + e);
            if ((unsigned)c >= NN) c = 0;
            int p = atomicAdd(&g_cursor[r], 1);
            g_col[p] = c;
        }
    }
}

// ================= weight split prep: W[K,N] -> Bh/Bl[N,K] bf16 =================
template <int WID, int Nw, int Kw>
__global__ void k_wprep(const float* __restrict__ W) {
    unsigned short* wh = const_cast<unsigned short*>(sel_wh(WID));
    unsigned short* wl = const_cast<unsigned short*>(sel_wl(WID));
    int i = blockIdx.x * blockDim.x + threadIdx.x;
    if (i >= Nw * Kw) return;
    int n = i / Kw, k = i % Kw;
    float v = W[(size_t)k * Nw + n];
    __nv_bfloat16 h = __float2bfloat16_rn(v);
    float res = v - __bfloat162float(h);
    __nv_bfloat16 l = __float2bfloat16_rn(res);
    wh[i] = __bfloat16_as_ushort(h);
    wl[i] = __bfloat16_as_ushort(l);
}

// ================= mma.sync split GEMM =================
// C[128x128 tile] = A(fp32 -> bf16 hi/lo) @ W(pre-split bf16 [N,K])^T
// 3 products: Ah*Bh + Ah*Bl + Al*Bh. 8 warps: 4(m) x 2(n), warp tile 32x64.
// smem stage: Ah | Al | Bh | Bl, each 128 rows x 24 bf16 (48B padded, conflict-free).
#define ROWB 48
#define MATB (128 * ROWB)      // 6144
#define STAGEB (4 * MATB)      // 24576

template <int ASRC, int WID, int OUT16, bool SCALE, bool BIAS, int NT, int KK>
__global__ void __launch_bounds__(256, 1)
k_mgemm(const float* __restrict__ Aarg, const float* __restrict__ bias,
        float* __restrict__ Carg) {
    __shared__ __align__(16) unsigned char smem[2 * STAGEB];

    const float* A = sel_af(ASRC, Aarg);
    const unsigned short* Wh = sel_wh(WID);
    const unsigned short* Wl = sel_wl(WID);

    int tid = threadIdx.x;
    int wid = tid >> 5, lane = tid & 31;
    int wm = wid & 3, wn = wid >> 2;
    int bm = blockIdx.x * 128, bn = blockIdx.y * 128;

    // global load mapping: 2 threads per row, 8 k each
    int grow = tid >> 1;
    int gkq  = (tid & 1) * 8;
    bool aval = (bm + grow) < NN;
    const float*          Ap  = A  + (size_t)(bm + grow) * KK + gkq;
    const unsigned short* Bph = Wh + (size_t)(bn + grow) * KK + gkq;
    const unsigned short* Bpl = Wl + (size_t)(bn + grow) * KK + gkq;

    uint32_t sb = smem_u32(smem);
    uint32_t stA = sb + grow * ROWB + gkq * 2;          // store addr (Ah)
    uint32_t stB = sb + 2 * MATB + grow * ROWB + gkq * 2;  // (Bh)

    // ldmatrix source mapping
    int lrow = lane & 15, lcolb = (lane >> 4) * 16;     // col-half byte offset
    uint32_t ldA = sb + (wm * 32 + lrow) * ROWB + lcolb;
    uint32_t ldB = sb + 2 * MATB + (wn * 64 + lrow) * ROWB + lcolb;

    float c[2][8][4];
#pragma unroll
    for (int i = 0; i < 2; i++)
#pragma unroll
        for (int j = 0; j < 8; j++)
#pragma unroll
            for (int q = 0; q < 4; q++) c[i][j][q] = 0.f;

    float4 av0, av1;
    uint4 bvh, bvl;

    auto gload = [&](int k0) {
        av0 = aval ? *(const float4*)(Ap + k0)     : make_float4(0.f, 0.f, 0.f, 0.f);
        av1 = aval ? *(const float4*)(Ap + k0 + 4) : make_float4(0.f, 0.f, 0.f, 0.f);
        bvh = *(const uint4*)(Bph + k0);
        bvl = *(const uint4*)(Bpl + k0);
    };
    auto sstore = [&](int s) {
        uint32_t hi[4], lo[4];
        float f[8] = {av0.x, av0.y, av0.z, av0.w, av1.x, av1.y, av1.z, av1.w};
#pragma unroll
        for (int j = 0; j < 4; j++) {
            __nv_bfloat16 h0 = __float2bfloat16_rn(f[2 * j]);
            __nv_bfloat16 h1 = __float2bfloat16_rn(f[2 * j + 1]);
            __nv_bfloat16 l0 = __float2bfloat16_rn(f[2 * j] - __bfloat162float(h0));
            __nv_bfloat16 l1 = __float2bfloat16_rn(f[2 * j + 1] - __bfloat162float(h1));
            hi[j] = (uint32_t)__bfloat16_as_ushort(h0) | ((uint32_t)__bfloat16_as_ushort(h1) << 16);
            lo[j] = (uint32_t)__bfloat16_as_ushort(l0) | ((uint32_t)__bfloat16_as_ushort(l1) << 16);
        }
        uint32_t base = s * STAGEB;
        *(uint4*)(smem + (stA - sb) + base)        = *(uint4*)hi;
        *(uint4*)(smem + (stA - sb) + base + MATB) = *(uint4*)lo;
        *(uint4*)(smem + (stB - sb) + base)        = bvh;
        *(uint4*)(smem + (stB - sb) + base + MATB) = bvl;
    };

    gload(0);
    sstore(0);

    const int NSTEP = KK / 16;
    int s = 0;
    for (int step = 0; step < NSTEP; step++) {
        __syncthreads();
        bool more = (step + 1) < NSTEP;
        if (more) gload((step + 1) * 16);

        uint32_t base = s * STAGEB;
        uint32_t ah[2][4], al[2][4];
#pragma unroll
        for (int mt = 0; mt < 2; mt++) {
            uint32_t a = ldA + base + mt * 16 * ROWB;
            LDSM4(ah[mt], a);
            LDSM4(al[mt], a + MATB);
        }
        uint32_t bh[4][4], bl[4][4];
#pragma unroll
        for (int g = 0; g < 4; g++) {
            uint32_t a = ldB + base + g * 16 * ROWB;
            LDSM4(bh[g], a);
            LDSM4(bl[g], a + MATB);
        }
#pragma unroll
        for (int mt = 0; mt < 2; mt++)
#pragma unroll
            for (int g = 0; g < 4; g++) {
                // n-tile 0 of group: B regs {r0, r2}; n-tile 1: {r1, r3}
                mma16816(c[mt][g * 2],     ah[mt], bh[g][0], bh[g][2]);
                mma16816(c[mt][g * 2],     ah[mt], bl[g][0], bl[g][2]);
                mma16816(c[mt][g * 2],     al[mt], bh[g][0], bh[g][2]);
                mma16816(c[mt][g * 2 + 1], ah[mt], bh[g][1], bh[g][3]);
                mma16816(c[mt][g * 2 + 1], ah[mt], bl[g][1], bl[g][3]);
                mma16816(c[mt][g * 2 + 1], al[mt], bh[g][1], bh[g][3]);
            }
        if (more) sstore(s ^ 1);
        s ^= 1;
    }

    // ---- epilogue ----
#pragma unroll
    for (int mt = 0; mt < 2; mt++) {
#pragma unroll
        for (int n8 = 0; n8 < 8; n8++) {
            int col = bn + wn * 64 + n8 * 8 + (lane & 3) * 2;
#pragma unroll
            for (int h = 0; h < 2; h++) {
                int r = bm + wm * 32 + mt * 16 + (lane >> 2) + h * 8;
                if (r >= NN) continue;
                float v0 = c[mt][n8][2 * h], v1 = c[mt][n8][2 * h + 1];
                if (OUT16 != 0) {
                    float sc = g_dinv[r];
                    __half2 hv = __floats2half2_rn(v0 * sc, v1 * sc);
                    *(__half2*)(sel_d16(OUT16) + (size_t)r * NT + col) = hv;
                } else {
                    if (BIAS) { v0 += bias[col]; v1 += bias[col + 1]; }
                    *(float2*)(Carg + (size_t)r * NT + col) = make_float2(v0, v1);
                }
            }
        }
    }
}

// ================= propagate: fp16 gather =================
template <int F, bool RELU, int SRC, int ZDST>
__global__ void k_prop(const float* __restrict__ bias) {
    const int L = F / 8;
    int node = blockIdx.x * blockDim.y + threadIdx.y;
    if (node >= NN) return;
    const uint4* xw = (const uint4*)((SRC == 1) ? g_xw1h : g_xw2h);
    float* z = (ZDST == 1) ? g_z1 : g_z2;
    int f = threadIdx.x;

    float2 a0 = {0.f, 0.f}, a1 = {0.f, 0.f}, a2 = {0.f, 0.f}, a3 = {0.f, 0.f};
    {
        uint4 u = xw[(size_t)node * L + f];
        float2 t;
        t = __half22float2(*(__half2*)&u.x); a0.x += t.x; a0.y += t.y;
        t = __half22float2(*(__half2*)&u.y); a1.x += t.x; a1.y += t.y;
        t = __half22float2(*(__half2*)&u.z); a2.x += t.x; a2.y += t.y;
        t = __half22float2(*(__half2*)&u.w); a3.x += t.x; a3.y += t.y;
    }
    int s = g_rowptr[node], e = g_rowptr[node + 1];
    for (int k = s; k < e; k++) {
        int c = __ldg(&g_col[k]);
        uint4 u = xw[(size_t)c * L + f];
        float2 t;
        t = __half22float2(*(__half2*)&u.x); a0.x += t.x; a0.y += t.y;
        t = __half22float2(*(__half2*)&u.y); a1.x += t.x; a1.y += t.y;
        t = __half22float2(*(__half2*)&u.z); a2.x += t.x; a2.y += t.y;
        t = __half22float2(*(__half2*)&u.w); a3.x += t.x; a3.y += t.y;
    }
    float di = g_dinv[node];
    float4 b0 = *(const float4*)(bias + f * 8);
    float4 b1 = *(const float4*)(bias + f * 8 + 4);
    float o[8];
    o[0] = di * a0.x + b0.x; o[1] = di * a0.y + b0.y;
    o[2] = di * a1.x + b0.z; o[3] = di * a1.y + b0.w;
    o[4] = di * a2.x + b1.x; o[5] = di * a2.y + b1.y;
    o[6] = di * a3.x + b1.z; o[7] = di * a3.y + b1.w;
    if (RELU) {
#pragma unroll
        for (int j = 0; j < 8; j++) o[j] = fmaxf(o[j], 0.f);
    }
    float* dst = z + (size_t)node * F + f * 8;
    *(float4*)dst = make_float4(o[0], o[1], o[2], o[3]);
    *(float4*)(dst + 4) = make_float4(o[4], o[5], o[6], o[7]);
}

// ================= launch =================
extern "C" void kernel_launch(void* const* d_in, const int* in_sizes, int n_in,
                              void* d_out, int out_size) {
    const float* x   = (const float*)d_in[0];
    const void*  ei  = d_in[1];
    const float* W1  = (const float*)d_in[2];
    const float* b1  = (const float*)d_in[3];
    const float* W2  = (const float*)d_in[4];
    const float* b2  = (const float*)d_in[5];
    const float* Wmu = (const float*)d_in[6];
    const float* bmu = (const float*)d_in[7];
    const float* Wlv = (const float*)d_in[8];
    const float* blv = (const float*)d_in[9];
    float* out = (float*)d_out;

    int E = in_sizes[1] / 2;

    // graph prep
    k_detect<<<1, 256>>>((const int*)ei, E);
    k_zero_deg<<<(NN + 255) / 256, 256>>>();
    k_count<<<(E + 255) / 256, 256>>>(ei, E);
    k_reduce<<<SCAN_B, 256>>>();
    k_scan_bsums<<<1, 128>>>();
    k_scan_final<<<SCAN_B, 256>>>();
    k_fill<<<(E + 255) / 256, 256>>>(ei, E);

    // weight splits
    k_wprep<1, 256, 256><<<(256 * 256 + 255) / 256, 256>>>(W1);
    k_wprep<2, 128, 256><<<(128 * 256 + 255) / 256, 256>>>(W2);
    k_wprep<3, 128, 128><<<(128 * 128 + 255) / 256, 256>>>(Wmu);
    k_wprep<4, 128, 128><<<(128 * 128 + 255) / 256, 256>>>(Wlv);

    const int GM = (NN + 127) / 128;  // 782

    // layer 1: xw1h = dinv * (x @ W1) [fp16] ; z1 = relu(prop + b1)
    k_mgemm<0, 1, 1, true, false, 256, 256><<<dim3(GM, 2), 256>>>(x, nullptr, nullptr);
    k_prop<256, true, 1, 1><<<(NN + 7) / 8, dim3(32, 8)>>>(b1);

    // layer 2: xw2h = dinv * (z1 @ W2) [fp16] ; z2 = prop + b2
    k_mgemm<2, 2, 2, true, false, 128, 256><<<dim3(GM, 1), 256>>>(nullptr, nullptr, nullptr);
    k_prop<128, false, 2, 2><<<(NN + 15) / 16, dim3(16, 16)>>>(b2);

    // heads
    k_mgemm<4, 3, 0, false, true, 128, 128><<<dim3(GM, 1), 256>>>(nullptr, bmu, out);
    k_mgemm<4, 4, 0, false, true, 128, 128><<<dim3(GM, 1), 256>>>(nullptr, blv, out + (size_t)NN * 128);
}

// round 7
// speedup vs baseline: 2.6322x; 1.0527x over previous
#include <cuda_runtime.h>
#include <cuda_fp16.h>
#include <cuda_bf16.h>
#include <cstdint>

#define NN 100000
#define MAXE 3200000
#define SCAN_B 100
#define SCAN_CH 1000

// ---- static scratch ----
__device__ int   g_is64;
__device__ int   g_deg[NN];
__device__ int   g_rowptr[NN + 1];
__device__ int   g_cursor[NN];
__device__ int   g_col[MAXE];
__device__ float g_dinv[NN];
__device__ int   g_bsum[SCAN_B];

// activations
__device__ __half g_xw1h[(size_t)NN * 256];
__device__ __half g_xw2h[(size_t)NN * 128];
__device__ float  g_z1 [(size_t)NN * 256];
__device__ float  g_z2 [(size_t)NN * 128];

// weight splits, [N,K] layout, bf16 hi/lo.  heads = Wmu|Wlv stacked (256 rows x 128 K)
__device__ unsigned short g_w1h[256 * 256], g_w1l[256 * 256];
__device__ unsigned short g_w2h[128 * 256], g_w2l[128 * 256];
__device__ unsigned short g_whh[256 * 128], g_whl[256 * 128];

__device__ __forceinline__ const unsigned short* sel_wh(int id) {
    switch (id) { case 1: return g_w1h; case 2: return g_w2h; default: return g_whh; }
}
__device__ __forceinline__ const unsigned short* sel_wl(int id) {
    switch (id) { case 1: return g_w1l; case 2: return g_w2l; default: return g_whl; }
}
__device__ __forceinline__ const float* sel_af(int id, const float* arg) {
    switch (id) { case 2: return g_z1; case 4: return g_z2; default: return arg; }
}
__device__ __forceinline__ __half* sel_d16(int id) {
    return (id == 1) ? g_xw1h : g_xw2h;
}

__device__ __forceinline__ uint32_t smem_u32(const void* p) {
    uint32_t a;
    asm("{ .reg .u64 t; cvta.to.shared.u64 t, %1; cvt.u32.u64 %0, t; }"
        : "=r"(a) : "l"(p));
    return a;
}

#define LDSM4(r, addr)                                                         \
    asm volatile("ldmatrix.sync.aligned.m8n8.x4.shared.b16 {%0,%1,%2,%3}, [%4];" \
                 : "=r"((r)[0]), "=r"((r)[1]), "=r"((r)[2]), "=r"((r)[3])      \
                 : "r"(addr))

__device__ __forceinline__ void mma16816(float* c, const uint32_t* a,
                                         uint32_t b0, uint32_t b1) {
    asm volatile(
        "mma.sync.aligned.m16n8k16.row.col.f32.bf16.bf16.f32 "
        "{%0,%1,%2,%3}, {%4,%5,%6,%7}, {%8,%9}, {%0,%1,%2,%3};"
        : "+f"(c[0]), "+f"(c[1]), "+f"(c[2]), "+f"(c[3])
        : "r"(a[0]), "r"(a[1]), "r"(a[2]), "r"(a[3]), "r"(b0), "r"(b1));
}

// ================= prep: zero deg + dtype detect (one kernel) =================
__global__ void k_init(const int* __restrict__ ei32, int E) {
    int i = blockIdx.x * blockDim.x + threadIdx.x;
    if (i < NN) g_deg[i] = 0;
    if (blockIdx.x == 0) {
        __shared__ int bad;
        if (threadIdx.x == 0) bad = 0;
        __syncthreads();
        int n = min(E, 2048);
        for (int j = threadIdx.x; j < n; j += blockDim.x)
            if (ei32[2 * j + 1] != 0) bad = 1;
        __syncthreads();
        if (threadIdx.x == 0) g_is64 = bad ? 0 : 1;
    }
}
__device__ __forceinline__ int load_idx(const void* ei, long long pos) {
    if (g_is64) return (int)((const long long*)ei)[pos];
    return ((const int*)ei)[pos];
}
__global__ void k_count(const void* __restrict__ ei, int E) {
    int e = blockIdx.x * blockDim.x + threadIdx.x;
    if (e < E) {
        int r = load_idx(ei, e);
        if ((unsigned)r < NN) atomicAdd(&g_deg[r], 1);
    }
}
__global__ void k_reduce() {
    __shared__ int sh[256];
    int b = blockIdx.x, t = threadIdx.x, s = 0, base = b * SCAN_CH;
    for (int i = t; i < SCAN_CH; i += 256) s += g_deg[base + i];
    sh[t] = s;
    __syncthreads();
    for (int off = 128; off > 0; off >>= 1) {
        if (t < off) sh[t] += sh[t + off];
        __syncthreads();
    }
    if (t == 0) g_bsum[b] = sh[0];
}
// per-block: prefix over g_bsum (100 ints, cheap) + local scan + rowptr/cursor/dinv
__global__ void k_scan_final() {
    __shared__ int ps[256];
    __shared__ int blkoff;
    int b = blockIdx.x, t = threadIdx.x, base = b * SCAN_CH;
    if (t == 0) {
        int o = 0;
        for (int j = 0; j < b; j++) o += g_bsum[j];
        blkoff = o;
        if (b == SCAN_B - 1) g_rowptr[NN] = o + g_bsum[b];
    }
    int d[4], my = 0;
    if (t < 250) {
#pragma unroll
        for (int j = 0; j < 4; j++) { d[j] = g_deg[base + t * 4 + j]; my += d[j]; }
    }
    ps[t] = my;
    __syncthreads();
    for (int off = 1; off < 256; off <<= 1) {
        int u = (t >= off) ? ps[t - off] : 0;
        __syncthreads();
        ps[t] += u;
        __syncthreads();
    }
    if (t < 250) {
        int run = blkoff + ps[t] - my;
#pragma unroll
        for (int j = 0; j < 4; j++) {
            int i = base + t * 4 + j;
            g_rowptr[i] = run;
            g_cursor[i] = run;
            g_dinv[i]   = rsqrtf((float)(d[j] + 1));
            run += d[j];
        }
    }
}
__global__ void k_fill(const void* __restrict__ ei, int E) {
    int e = blockIdx.x * blockDim.x + threadIdx.x;
    if (e < E) {
        int r = load_idx(ei, e);
        if ((unsigned)r < NN) {
            int c = load_idx(ei, (long long)E + e);
            if ((unsigned)c >= NN) c = 0;
            int p = atomicAdd(&g_cursor[r], 1);
            g_col[p] = c;
        }
    }
}

// ================= merged weight split =================
// y=0: W1[256,256] -> g_w1*;  y=1: W2[256,128] -> g_w2*;  y=2: heads -> g_wh*
__global__ void k_wprep(const float* __restrict__ W1, const float* __restrict__ W2,
                        const float* __restrict__ Wmu, const float* __restrict__ Wlv) {
    int y = blockIdx.y;
    int i = blockIdx.x * blockDim.x + threadIdx.x;
    float v;
    unsigned short *wh, *wl;
    if (y == 0) {
        if (i >= 256 * 256) return;
        int n = i >> 8, k = i & 255;
        v = W1[(size_t)k * 256 + n];
        wh = g_w1h; wl = g_w1l;
    } else if (y == 1) {
        if (i >= 128 * 256) return;
        int n = i >> 8, k = i & 255;
        v = W2[(size_t)k * 128 + n];
        wh = g_w2h; wl = g_w2l;
    } else {
        if (i >= 256 * 128) return;
        int n = i >> 7, k = i & 127;
        v = (n < 128) ? Wmu[(size_t)k * 128 + n] : Wlv[(size_t)k * 128 + (n - 128)];
        wh = g_whh; wl = g_whl;
    }
    __nv_bfloat16 h = __float2bfloat16_rn(v);
    __nv_bfloat16 l = __float2bfloat16_rn(v - __bfloat162float(h));
    wh[i] = __bfloat16_as_ushort(h);
    wl[i] = __bfloat16_as_ushort(l);
}

// ================= mma.sync split GEMM =================
#define ROWB 48
#define MATB (128 * ROWB)
#define STAGEB (4 * MATB)

template <int ASRC, int WID, int OUT16, bool BIAS, bool HEADS, int NT, int KK>
__global__ void __launch_bounds__(256, 1)
k_mgemm(const float* __restrict__ Aarg, const float* __restrict__ bias,
        const float* __restrict__ bias2, float* __restrict__ Carg) {
    __shared__ __align__(16) unsigned char smem[2 * STAGEB];

    const float* A = sel_af(ASRC, Aarg);
    const unsigned short* Wh = sel_wh(WID);
    const unsigned short* Wl = sel_wl(WID);

    int tid = threadIdx.x;
    int wid = tid >> 5, lane = tid & 31;
    int wm = wid & 3, wn = wid >> 2;
    int bm = blockIdx.x * 128, bn = blockIdx.y * 128;

    int grow = tid >> 1;
    int gkq  = (tid & 1) * 8;
    bool aval = (bm + grow) < NN;
    const float*          Ap  = A  + (size_t)(bm + grow) * KK + gkq;
    const unsigned short* Bph = Wh + (size_t)(bn + grow) * KK + gkq;
    const unsigned short* Bpl = Wl + (size_t)(bn + grow) * KK + gkq;

    uint32_t sb = smem_u32(smem);
    uint32_t stA = sb + grow * ROWB + gkq * 2;
    uint32_t stB = sb + 2 * MATB + grow * ROWB + gkq * 2;

    int lrow = lane & 15, lcolb = (lane >> 4) * 16;
    uint32_t ldA = sb + (wm * 32 + lrow) * ROWB + lcolb;
    uint32_t ldB = sb + 2 * MATB + (wn * 64 + lrow) * ROWB + lcolb;

    float c[2][8][4];
#pragma unroll
    for (int i = 0; i < 2; i++)
#pragma unroll
        for (int j = 0; j < 8; j++)
#pragma unroll
            for (int q = 0; q < 4; q++) c[i][j][q] = 0.f;

    float4 av0, av1;
    uint4 bvh, bvl;

    auto gload = [&](int k0) {
        av0 = aval ? *(const float4*)(Ap + k0)     : make_float4(0.f, 0.f, 0.f, 0.f);
        av1 = aval ? *(const float4*)(Ap + k0 + 4) : make_float4(0.f, 0.f, 0.f, 0.f);
        bvh = *(const uint4*)(Bph + k0);
        bvl = *(const uint4*)(Bpl + k0);
    };
    auto sstore = [&](int s) {
        uint32_t hi[4], lo[4];
        float f[8] = {av0.x, av0.y, av0.z, av0.w, av1.x, av1.y, av1.z, av1.w};
#pragma unroll
        for (int j = 0; j < 4; j++) {
            __nv_bfloat16 h0 = __float2bfloat16_rn(f[2 * j]);
            __nv_bfloat16 h1 = __float2bfloat16_rn(f[2 * j + 1]);
            __nv_bfloat16 l0 = __float2bfloat16_rn(f[2 * j] - __bfloat162float(h0));
            __nv_bfloat16 l1 = __float2bfloat16_rn(f[2 * j + 1] - __bfloat162float(h1));
            hi[j] = (uint32_t)__bfloat16_as_ushort(h0) | ((uint32_t)__bfloat16_as_ushort(h1) << 16);
            lo[j] = (uint32_t)__bfloat16_as_ushort(l0) | ((uint32_t)__bfloat16_as_ushort(l1) << 16);
        }
        uint32_t base = s * STAGEB;
        *(uint4*)(smem + (stA - sb) + base)        = *(uint4*)hi;
        *(uint4*)(smem + (stA - sb) + base + MATB) = *(uint4*)lo;
        *(uint4*)(smem + (stB - sb) + base)        = bvh;
        *(uint4*)(smem + (stB - sb) + base + MATB) = bvl;
    };

    gload(0);
    sstore(0);

    const int NSTEP = KK / 16;
    int s = 0;
    for (int step = 0; step < NSTEP; step++) {
        __syncthreads();
        bool more = (step + 1) < NSTEP;
        if (more) gload((step + 1) * 16);

        uint32_t base = s * STAGEB;
        uint32_t ah[2][4], al[2][4];
#pragma unroll
        for (int mt = 0; mt < 2; mt++) {
            uint32_t a = ldA + base + mt * 16 * ROWB;
            LDSM4(ah[mt], a);
            LDSM4(al[mt], a + MATB);
        }
        uint32_t bh[4][4], bl[4][4];
#pragma unroll
        for (int g = 0; g < 4; g++) {
            uint32_t a = ldB + base + g * 16 * ROWB;
            LDSM4(bh[g], a);
            LDSM4(bl[g], a + MATB);
        }
#pragma unroll
        for (int mt = 0; mt < 2; mt++)
#pragma unroll
            for (int g = 0; g < 4; g++) {
                mma16816(c[mt][g * 2],     ah[mt], bh[g][0], bh[g][2]);
                mma16816(c[mt][g * 2],     ah[mt], bl[g][0], bl[g][2]);
                mma16816(c[mt][g * 2],     al[mt], bh[g][0], bh[g][2]);
                mma16816(c[mt][g * 2 + 1], ah[mt], bh[g][1], bh[g][3]);
                mma16816(c[mt][g * 2 + 1], ah[mt], bl[g][1], bl[g][3]);
                mma16816(c[mt][g * 2 + 1], al[mt], bh[g][1], bh[g][3]);
            }
        if (more) sstore(s ^ 1);
        s ^= 1;
    }

    // ---- epilogue ----
    const float* bs = (HEADS && bn >= 128) ? bias2 : bias;
    float* cbase = HEADS ? (Carg + (bn >= 128 ? (size_t)NN * 128 : 0)) : Carg;
#pragma unroll
    for (int mt = 0; mt < 2; mt++) {
#pragma unroll
        for (int n8 = 0; n8 < 8; n8++) {
            int col = bn + wn * 64 + n8 * 8 + (lane & 3) * 2;
            int lcol = HEADS ? (col & 127) : col;
#pragma unroll
            for (int h = 0; h < 2; h++) {
                int r = bm + wm * 32 + mt * 16 + (lane >> 2) + h * 8;
                if (r >= NN) continue;
                float v0 = c[mt][n8][2 * h], v1 = c[mt][n8][2 * h + 1];
                if (OUT16 != 0) {
                    float sc = g_dinv[r];
                    __half2 hv = __floats2half2_rn(v0 * sc, v1 * sc);
                    *(__half2*)(sel_d16(OUT16) + (size_t)r * NT + col) = hv;
                } else {
                    if (BIAS) { v0 += bs[lcol]; v1 += bs[lcol + 1]; }
                    int nt = HEADS ? 128 : NT;
                    *(float2*)(cbase + (size_t)r * nt + lcol) = make_float2(v0, v1);
                }
            }
        }
    }
}

// ================= propagate: fp16 gather, 4x unrolled =================
template <int F, bool RELU, int SRC, int ZDST>
__global__ void k_prop(const float* __restrict__ bias) {
    const int L = F / 8;
    int node = blockIdx.x * blockDim.y + threadIdx.y;
    if (node >= NN) return;
    const uint4* xw = (const uint4*)((SRC == 1) ? g_xw1h : g_xw2h);
    float* z = (ZDST == 1) ? g_z1 : g_z2;
    int f = threadIdx.x;

    float2 a0 = {0.f, 0.f}, a1 = {0.f, 0.f}, a2 = {0.f, 0.f}, a3 = {0.f, 0.f};
    auto accum = [&](uint4 u) {
        float2 t;
        t = __half22float2(*(__half2*)&u.x); a0.x += t.x; a0.y += t.y;
        t = __half22float2(*(__half2*)&u.y); a1.x += t.x; a1.y += t.y;
        t = __half22float2(*(__half2*)&u.z); a2.x += t.x; a2.y += t.y;
        t = __half22float2(*(__half2*)&u.w); a3.x += t.x; a3.y += t.y;
    };
    accum(xw[(size_t)node * L + f]);  // self loop

    int s = g_rowptr[node], e = g_rowptr[node + 1];
    int k = s;
    for (; k + 4 <= e; k += 4) {
        int c0 = __ldg(&g_col[k + 0]);
        int c1 = __ldg(&g_col[k + 1]);
        int c2 = __ldg(&g_col[k + 2]);
        int c3 = __ldg(&g_col[k + 3]);
        uint4 u0 = xw[(size_t)c0 * L + f];
        uint4 u1 = xw[(size_t)c1 * L + f];
        uint4 u2 = xw[(size_t)c2 * L + f];
        uint4 u3 = xw[(size_t)c3 * L + f];
        accum(u0); accum(u1); accum(u2); accum(u3);
    }
    for (; k < e; k++) {
        int c = __ldg(&g_col[k]);
        accum(xw[(size_t)c * L + f]);
    }

    float di = g_dinv[node];
    float4 b0 = *(const float4*)(bias + f * 8);
    float4 b1 = *(const float4*)(bias + f * 8 + 4);
    float o[8];
    o[0] = di * a0.x + b0.x; o[1] = di * a0.y + b0.y;
    o[2] = di * a1.x + b0.z; o[3] = di * a1.y + b0.w;
    o[4] = di * a2.x + b1.x; o[5] = di * a2.y + b1.y;
    o[6] = di * a3.x + b1.z; o[7] = di * a3.y + b1.w;
    if (RELU) {
#pragma unroll
        for (int j = 0; j < 8; j++) o[j] = fmaxf(o[j], 0.f);
    }
    float* dst = z + (size_t)node * F + f * 8;
    *(float4*)dst = make_float4(o[0], o[1], o[2], o[3]);
    *(float4*)(dst + 4) = make_float4(o[4], o[5], o[6], o[7]);
}

// ================= launch =================
extern "C" void kernel_launch(void* const* d_in, const int* in_sizes, int n_in,
                              void* d_out, int out_size) {
    const float* x   = (const float*)d_in[0];
    const void*  ei  = d_in[1];
    const float* W1  = (const float*)d_in[2];
    const float* b1  = (const float*)d_in[3];
    const float* W2  = (const float*)d_in[4];
    const float* b2  = (const float*)d_in[5];
    const float* Wmu = (const float*)d_in[6];
    const float* bmu = (const float*)d_in[7];
    const float* Wlv = (const float*)d_in[8];
    const float* blv = (const float*)d_in[9];
    float* out = (float*)d_out;

    int E = in_sizes[1] / 2;

    // graph prep (5 launches)
    k_init<<<(NN + 255) / 256, 256>>>((const int*)ei, E);
    k_count<<<(E + 255) / 256, 256>>>(ei, E);
    k_reduce<<<SCAN_B, 256>>>();
    k_scan_final<<<SCAN_B, 256>>>();
    k_fill<<<(E + 255) / 256, 256>>>(ei, E);

    // all weight splits in one launch
    k_wprep<<<dim3(256, 3), 256>>>(W1, W2, Wmu, Wlv);

    const int GM = (NN + 127) / 128;  // 782

    // layer 1
    k_mgemm<0, 1, 1, false, false, 256, 256><<<dim3(GM, 2), 256>>>(x, nullptr, nullptr, nullptr);
    k_prop<256, true, 1, 1><<<(NN + 7) / 8, dim3(32, 8)>>>(b1);

    // layer 2
    k_mgemm<2, 2, 2, false, false, 128, 256><<<dim3(GM, 1), 256>>>(nullptr, nullptr, nullptr, nullptr);
    k_prop<128, false, 2, 2><<<(NN + 15) / 16, dim3(16, 16)>>>(b2);

    // merged heads: y=0 -> mu, y=1 -> lv
    k_mgemm<4, 3, 0, true, true, 128, 128><<<dim3(GM, 2), 256>>>(nullptr, bmu, blv, out);
}